// round 14
// baseline (speedup 1.0000x reference)
#include <cuda_runtime.h>
#include <cuda_bf16.h>
#include <cstdint>

#define NCC 68
#define SCALEF 0.125f

// ---------------- device scratch ----------------
__device__ float g_cbe[NCC*128];
__device__ float g_qg[12*128];
__device__ float g_qe[12*128];
__device__ float g_pe[24*128];
__device__ float g_cKe[24];
__device__ float g_MTg[12*2*128*128];
__device__ float g_cg[12*128];
__device__ float g_MTe[2*128*128];
__device__ float g_ce[128];
__device__ float g_coef2[206*5];
__device__ int   g_mm_cc[206];
__device__ float g_T[206*5*128];
__device__ float g_xbar[8192*12*256];
__device__ float g_r[8192*12*128];
__device__ unsigned short g_Bh2[128*256];
__device__ unsigned short g_Bl2[128*256];

__device__ __forceinline__ int grp_n(int i){ return i<5?7:(i<10?9:(i==10?17:6)); }
__device__ __forceinline__ int grp_s(int i){ return 2*(i<5? 7*i : (i<10? 35+9*(i-5) : (i==10? 80 : 97))); }
__device__ __forceinline__ int grp_off(int i){ int m=i%5; return m==0?3:(m==1?4:(m==2?2:(m==3?1:0))); }
__device__ __forceinline__ int member_cc(int i,int j){ return i<10 ? 5*j+grp_off(i) : (i==10?45+j:62+j); }
__device__ __forceinline__ int orig_ch(int cc){ return cc<45?cc:cc+20; }
__device__ __forceinline__ void m_decode(int m,int&ih,int&g,int&cc){
  for(int i=0;i<12;i++){ int n=grp_n(i); if(m<2*n){ int h=m/n; g=m%n; ih=2*i+h; cc=member_cc(i,g); return;} m-=2*n; }
  ih=0;g=0;cc=0;
}

// ---------------- setup A ----------------
__global__ void k_setupA(const float* __restrict__ cb,const float* __restrict__ cemb,
    const float* __restrict__ cq,const float* __restrict__ gw,const float* __restrict__ gb,
    const float* __restrict__ gow,const float* __restrict__ gob,const float* __restrict__ eq,
    const float* __restrict__ ew,const float* __restrict__ eb,const float* __restrict__ eow,
    const float* __restrict__ eob){
  int idx = blockIdx.x*256+threadIdx.x;
  if(idx<8704){ int cc=idx>>7,d=idx&127,c=orig_ch(cc); g_cbe[idx]=cb[c*128+d]+cemb[c*128+d]; return;}
  idx-=8704;
  if(idx<1536){ int i=idx>>7,r=idx&127; float s=gb[i*384+r];
    const float* w=gw+(i*384+r)*128; const float* q=cq+i*128;
    for(int d=0;d<128;d++) s=fmaf(q[d],w[d],s); g_qg[i*128+r]=s; return;}
  idx-=1536;
  if(idx<1536){ int t=idx>>7,r=idx&127; float s=eb[r];
    const float* w=ew+r*128; const float* q=eq+t*128;
    for(int d=0;d<128;d++) s=fmaf(q[d],w[d],s); g_qe[t*128+r]=s; return;}
  idx-=1536;
  if(idx<393216){ int i=idx>>15, rem=idx&32767, h=rem>>14, dout=(rem>>7)&127, k=rem&127;
    float s=0.f; const float* gr=gow+i*16384+dout*128+h*64;
    for(int e=0;e<64;e++) s=fmaf(gr[e], gw[(i*384+256+h*64+e)*128+k], s);
    g_MTg[((i*2+h)*128+k)*128+dout]=s; return;}
  idx-=393216;
  if(idx<1536){ int i=idx>>7,dout=idx&127; float s=gob[i*128+dout];
    const float* gr=gow+i*16384+dout*128;
    for(int r=0;r<128;r++) s=fmaf(gr[r], gb[i*384+256+r], s); g_cg[idx]=s; return;}
  idx-=1536;
  if(idx<32768){ int h=idx>>14, dout=(idx>>7)&127, k=idx&127;
    float s=0.f; const float* er=eow+dout*128+h*64;
    for(int e=0;e<64;e++) s=fmaf(er[e], ew[(256+h*64+e)*128+k], s);
    g_MTe[(h*128+k)*128+dout]=s; return;}
  idx-=32768;
  if(idx<128){ float s=eob[idx]; const float* er=eow+idx*128;
    for(int r=0;r<128;r++) s=fmaf(er[r], eb[256+r], s); g_ce[idx]=s;}
}

// ---------------- setup C: score coefficients ----------------
__global__ void k_coef(const float* __restrict__ gw,const float* __restrict__ gb,
                       const float* __restrict__ conv_w){
  __shared__ float sred[4];
  int ih=blockIdx.x, i=ih>>1, h=ih&1, d=threadIdx.x;
  const float* q=g_qg+i*128+h*64;
  float pv=0.f;
  for(int e=0;e<64;e++) pv=fmaf(q[e], gw[(i*384+128+h*64+e)*128+d], pv);
  pv*=SCALEF;
  float ck=0.f;
  for(int e=0;e<64;e++) ck=fmaf(q[e], gb[i*384+128+h*64+e], ck);
  ck*=SCALEF;
  int n=grp_n(i), ms=grp_s(i)+h*n;
  for(int g=0;g<n;g++){
    int cc=member_cc(i,g);
    for(int p=0;p<5;p++){
      float w = (p<4)? conv_w[(orig_ch(cc)*4+p)*128+d] : g_cbe[cc*128+d];
      float v = pv*w;
      for(int off=16;off;off>>=1) v+=__shfl_xor_sync(0xffffffffu,v,off);
      if((d&31)==0) sred[d>>5]=v;
      __syncthreads();
      if(d==0){
        float s=sred[0]+sred[1]+sred[2]+sred[3];
        if(p==4) s+=ck;
        g_coef2[(ms+g)*5+p]=s;
        g_mm_cc[ms+g]=cc;
      }
      __syncthreads();
    }
  }
}

// ---------------- setup D ----------------
__global__ void k_misc(const float* __restrict__ conv_w,const float* __restrict__ ew,
                       const float* __restrict__ eb){
  int idx=blockIdx.x*256+threadIdx.x;
  if(idx<131840){
    int m=idx/640, p=(idx/128)%5, dout=idx&127;
    int ih,g,cc; m_decode(m,ih,g,cc);
    const float* M=g_MTg+ih*16384;
    float s=0.f;
    if(p<4){ const float* w=conv_w+(orig_ch(cc)*4+p)*128;
      for(int k=0;k<128;k++) s=fmaf(w[k], M[k*128+dout], s);
    } else { const float* w=g_cbe+cc*128;
      for(int k=0;k<128;k++) s=fmaf(w[k], M[k*128+dout], s);
    }
    g_T[idx]=s; return;
  }
  idx-=131840;
  if(idx<32768){
    int n=idx>>8, k=idx&255;
    float v=g_MTe[k*128+n];
    uint32_t hp; asm("cvt.rn.bf16x2.f32 %0,%1,%2;" : "=r"(hp) : "f"(0.f), "f"(v));
    float vh=__uint_as_float(hp<<16);
    float lo=v-vh;
    uint32_t lp; asm("cvt.rn.bf16x2.f32 %0,%1,%2;" : "=r"(lp) : "f"(0.f), "f"(lo));
    g_Bh2[n*256+k]=(unsigned short)(hp&0xffffu);
    g_Bl2[n*256+k]=(unsigned short)(lp&0xffffu);
    return;
  }
  idx-=32768;
  if(idx<3072){
    int th=idx>>7,d=idx&127,t=th>>1,h=th&1;
    float s=0.f; const float* q=g_qe+t*128+h*64;
    for(int e=0;e<64;e++) s=fmaf(q[e], ew[(128+h*64+e)*128+d], s);
    g_pe[idx]=s*SCALEF; return;
  }
  idx-=3072;
  if(idx<24){
    int t=idx>>1,h=idx&1; float s=0.f; const float* q=g_qe+t*128+h*64;
    for(int e=0;e<64;e++) s=fmaf(q[e], eb[128+h*64+e], s);
    g_cKe[idx]=s*SCALEF;
  }
}

// ---------------- K-main: 32 tokens x 6 groups per CTA (group-split), grid 512 ----------------
__global__ void __launch_bounds__(256,4) k_main(const float* __restrict__ x){
  extern __shared__ float sm[];
  float* sp  = sm;                 // 8704
  float* sa  = sm + 8704;          // up to 3776
  float* scf = sm + 12480;         // 1030
  int*   scc = (int*)(sm + 13510); // 206
  int tid=threadIdx.x;
  int tile=blockIdx.x>>1, half=blockIdx.x&1;
  int hp = tile>>2, wb = tile&3;
  int mlo = half? 88:0, mcnt = half? 118:88, ilo = half*6;
  for(int f=tid; f<8704; f+=256){
    int cc=f>>7, r=f&127, pi=r>>6, j=r&63, t=j>>1, pj=j&1;
    sp[(cc*4+pi*2+pj)*32+t] = x[orig_ch(cc)*32768 + (2*hp+pi)*256 + wb*64 + j];
  }
  for(int f=tid; f<1030; f+=256) scf[f]=g_coef2[f];
  if(tid<206) scc[tid]=g_mm_cc[tid];
  __syncthreads();
  // scores for my members
  for(int f=tid; f<mcnt*32; f+=256){
    int m=mlo+(f>>5), t=f&31;
    const float* cf=scf+m*5;
    const float* pb=sp+scc[m]*128;
    sa[f]=fmaf(cf[0],pb[t],fmaf(cf[1],pb[32+t],fmaf(cf[2],pb[64+t],fmaf(cf[3],pb[96+t],cf[4]))));
  }
  __syncthreads();
  // softmax per (i,h,t) for my 6 groups
  for(int f=tid; f<384; f+=256){
    int j=f>>5, t=f&31, i=ilo+(j>>1), h=j&1;
    int n=grp_n(i), st=grp_s(i)+h*n-mlo;
    float mx=-1e30f;
    for(int g=0;g<n;g++) mx=fmaxf(mx, sa[(st+g)*32+t]);
    float sum=0.f;
    for(int g=0;g<n;g++){ float e=__expf(sa[(st+g)*32+t]-mx); sa[(st+g)*32+t]=e; sum+=e; }
    float inv=1.f/sum;
    for(int g=0;g<n;g++) sa[(st+g)*32+t]*=inv;
  }
  __syncthreads();
  int d=tid&127, th=tid>>7;
  int l0=tile*32 + th*16;
  for(int ii=0;ii<6;ii++){
    int i=ilo+ii;
    float acc[16];
    float bias=g_cg[i*128+d];
    #pragma unroll
    for(int t=0;t<16;t++) acc[t]=bias;
    int st=grp_s(i), n=grp_n(i);
    for(int g=0;g<n;g++){
      int m0=st+g, m1=m0+n;
      const float* Ta=g_T+m0*640+d;
      const float* Tb=g_T+m1*640+d;
      float A0=Ta[0],A1=Ta[128],A2=Ta[256],A3=Ta[384],A4=Ta[512];
      float B0=Tb[0],B1=Tb[128],B2=Tb[256],B3=Tb[384],B4=Tb[512];
      const float* pb=sp+scc[m0]*128+th*16;
      const float* aa=sa+(m0-mlo)*32+th*16;
      const float* ab=sa+(m1-mlo)*32+th*16;
      #pragma unroll
      for(int q=0;q<4;q++){
        float4 p0=*(const float4*)(pb+q*4);
        float4 p1=*(const float4*)(pb+32+q*4);
        float4 p2=*(const float4*)(pb+64+q*4);
        float4 p3=*(const float4*)(pb+96+q*4);
        float4 av0=*(const float4*)(aa+q*4);
        float4 av1=*(const float4*)(ab+q*4);
        float ia,ib;
        ia=fmaf(A0,p0.x,fmaf(A1,p1.x,fmaf(A2,p2.x,fmaf(A3,p3.x,A4))));
        ib=fmaf(B0,p0.x,fmaf(B1,p1.x,fmaf(B2,p2.x,fmaf(B3,p3.x,B4))));
        acc[q*4+0]=fmaf(av0.x,ia,fmaf(av1.x,ib,acc[q*4+0]));
        ia=fmaf(A0,p0.y,fmaf(A1,p1.y,fmaf(A2,p2.y,fmaf(A3,p3.y,A4))));
        ib=fmaf(B0,p0.y,fmaf(B1,p1.y,fmaf(B2,p2.y,fmaf(B3,p3.y,B4))));
        acc[q*4+1]=fmaf(av0.y,ia,fmaf(av1.y,ib,acc[q*4+1]));
        ia=fmaf(A0,p0.z,fmaf(A1,p1.z,fmaf(A2,p2.z,fmaf(A3,p3.z,A4))));
        ib=fmaf(B0,p0.z,fmaf(B1,p1.z,fmaf(B2,p2.z,fmaf(B3,p3.z,B4))));
        acc[q*4+2]=fmaf(av0.z,ia,fmaf(av1.z,ib,acc[q*4+2]));
        ia=fmaf(A0,p0.w,fmaf(A1,p1.w,fmaf(A2,p2.w,fmaf(A3,p3.w,A4))));
        ib=fmaf(B0,p0.w,fmaf(B1,p1.w,fmaf(B2,p2.w,fmaf(B3,p3.w,B4))));
        acc[q*4+3]=fmaf(av0.w,ia,fmaf(av1.w,ib,acc[q*4+3]));
      }
    }
    #pragma unroll
    for(int t=0;t<16;t++)
      g_r[((l0+t)*12+i)*128+d]=acc[t];
  }
}

// ---------------- ensemble scores + obar ----------------
__global__ void k_ens1(){
  __shared__ float sout[1536];
  __shared__ float ssc[288];
  int tid=threadIdx.x, lane=tid&31, wid=tid>>5;
  int l=blockIdx.x;
  for(int f=tid; f<1536; f+=256) sout[f]=g_r[l*1536+f];
  __syncthreads();
  for(int dot=wid; dot<288; dot+=8){
    int th=dot/12, s=dot%12;
    const float* p=g_pe+th*128;
    const float* o=sout+s*128;
    float v=0.f;
    #pragma unroll
    for(int q=0;q<4;q++){ int dd=lane+32*q; v=fmaf(p[dd],o[dd],v); }
    for(int off=16;off;off>>=1) v+=__shfl_xor_sync(0xffffffffu,v,off);
    if(lane==0) ssc[dot]=v+g_cKe[th];
  }
  __syncthreads();
  if(tid<24){
    float* s=ssc+tid*12;
    float mx=-1e30f; for(int j=0;j<12;j++) mx=fmaxf(mx,s[j]);
    float sum=0.f; for(int j=0;j<12;j++){ float e=__expf(s[j]-mx); s[j]=e; sum+=e; }
    float inv=1.f/sum; for(int j=0;j<12;j++) s[j]*=inv;
  }
  __syncthreads();
  for(int o=tid;o<3072;o+=256){
    int d=o&127, th=o>>7;
    const float* w=ssc+th*12;
    float acc=0.f;
    #pragma unroll
    for(int s=0;s<12;s++) acc=fmaf(w[s], sout[s*128+d], acc);
    g_xbar[l*3072+th*128+d]=acc;
  }
}

// ---------------- HMMA GEMM + LayerNorm: 96 rows (8 tokens)/CTA ----------------
#define SPITCH 136
__global__ void __launch_bounds__(384,1) k_hmma_ln(const float* __restrict__ gamma,
    const float* __restrict__ beta, float* __restrict__ out){
  extern __shared__ unsigned short smu16[];
  unsigned short* Ah = smu16;
  unsigned short* Al = Ah + 96*SPITCH;
  unsigned short* Bh = Al + 96*SPITCH;
  unsigned short* Bl = Bh + 128*SPITCH;
  float* Cs = (float*)smu16;
  __shared__ float sred[384];
  __shared__ float smean[8], srstd[8];
  int tid=threadIdx.x, w=tid>>5, lane=tid&31;
  int mw=w>>2, nw=w&3, g=lane>>2, t=lane&3;
  size_t rowBase=(size_t)blockIdx.x*96;
  float c[2][4][4];
  #pragma unroll
  for(int mi=0;mi<2;mi++)
    #pragma unroll
    for(int ni=0;ni<4;ni++){ c[mi][ni][0]=0.f;c[mi][ni][1]=0.f;c[mi][ni][2]=0.f;c[mi][ni][3]=0.f; }

  for(int chunk=0; chunk<2; chunk++){
    if(chunk) __syncthreads();
    for(int f=tid; f<3072; f+=384){
      int row=f>>5, kq=f&31;
      float4 v=*(const float4*)(g_xbar + (rowBase+row)*256 + chunk*128 + kq*4);
      uint32_t h01,h23,l01,l23;
      asm("cvt.rn.bf16x2.f32 %0,%1,%2;" : "=r"(h01) : "f"(v.y), "f"(v.x));
      asm("cvt.rn.bf16x2.f32 %0,%1,%2;" : "=r"(h23) : "f"(v.w), "f"(v.z));
      float hx=__uint_as_float(h01<<16), hy=__uint_as_float(h01&0xffff0000u);
      float hz=__uint_as_float(h23<<16), hw=__uint_as_float(h23&0xffff0000u);
      asm("cvt.rn.bf16x2.f32 %0,%1,%2;" : "=r"(l01) : "f"(v.y-hy), "f"(v.x-hx));
      asm("cvt.rn.bf16x2.f32 %0,%1,%2;" : "=r"(l23) : "f"(v.w-hw), "f"(v.z-hz));
      uint32_t off=row*SPITCH + kq*4;
      *(uint32_t*)(Ah+off)=h01; *(uint32_t*)(Ah+off+2)=h23;
      *(uint32_t*)(Al+off)=l01; *(uint32_t*)(Al+off+2)=l23;
    }
    for(int f=tid; f<8192; f+=384){
      int n=f>>6, kp=(f&63)*2;
      *(uint32_t*)(Bh+n*SPITCH+kp)=*(const uint32_t*)(g_Bh2+n*256+chunk*128+kp);
      *(uint32_t*)(Bl+n*SPITCH+kp)=*(const uint32_t*)(g_Bl2+n*256+chunk*128+kp);
    }
    __syncthreads();
    #pragma unroll
    for(int prod=0; prod<3; prod++){
      const unsigned short* As = (prod<2)? Ah : Al;
      const unsigned short* Bs = (prod==1)? Bl : Bh;
      #pragma unroll
      for(int ks=0; ks<8; ks++){
        int kb = ks*16;
        uint32_t a[2][4];
        #pragma unroll
        for(int mi=0;mi<2;mi++){
          int r0 = mw*32 + mi*16;
          a[mi][0]=*(const uint32_t*)(As+(r0+g  )*SPITCH + kb + 2*t);
          a[mi][1]=*(const uint32_t*)(As+(r0+g+8)*SPITCH + kb + 2*t);
          a[mi][2]=*(const uint32_t*)(As+(r0+g  )*SPITCH + kb + 8 + 2*t);
          a[mi][3]=*(const uint32_t*)(As+(r0+g+8)*SPITCH + kb + 8 + 2*t);
        }
        uint32_t b[4][2];
        #pragma unroll
        for(int ni=0;ni<4;ni++){
          int n0 = nw*32 + ni*8 + g;
          b[ni][0]=*(const uint32_t*)(Bs+n0*SPITCH + kb + 2*t);
          b[ni][1]=*(const uint32_t*)(Bs+n0*SPITCH + kb + 8 + 2*t);
        }
        #pragma unroll
        for(int mi=0;mi<2;mi++)
          #pragma unroll
          for(int ni=0;ni<4;ni++){
            asm volatile("mma.sync.aligned.m16n8k16.row.col.f32.bf16.bf16.f32 "
              "{%0,%1,%2,%3},{%4,%5,%6,%7},{%8,%9},{%0,%1,%2,%3};"
              : "+f"(c[mi][ni][0]),"+f"(c[mi][ni][1]),"+f"(c[mi][ni][2]),"+f"(c[mi][ni][3])
              : "r"(a[mi][0]),"r"(a[mi][1]),"r"(a[mi][2]),"r"(a[mi][3]),
                "r"(b[ni][0]),"r"(b[ni][1]));
          }
      }
    }
  }
  __syncthreads();
  #pragma unroll
  for(int mi=0;mi<2;mi++){
    #pragma unroll
    for(int ni=0;ni<4;ni++){
      int col = nw*32 + ni*8 + 2*t;
      float bi0=g_ce[col], bi1=g_ce[col+1];
      int r0 = mw*32 + mi*16 + g;
      Cs[r0*128+col]    =c[mi][ni][0]+bi0; Cs[r0*128+col+1]    =c[mi][ni][1]+bi1;
      Cs[(r0+8)*128+col]=c[mi][ni][2]+bi0; Cs[(r0+8)*128+col+1]=c[mi][ni][3]+bi1;
    }
  }
  __syncthreads();
  int tt=tid/48, sub=tid%48;
  float s1=0.f;
  #pragma unroll
  for(int j=0;j<32;j++) s1+=Cs[tt*1536+sub+48*j];
  sred[tid]=s1;
  __syncthreads();
  if(w<8){
    float v=sred[w*48+lane]+((lane<16)? sred[w*48+32+lane] : 0.f);
    for(int off=16;off;off>>=1) v+=__shfl_xor_sync(0xffffffffu,v,off);
    if(lane==0) smean[w]=v*(1.f/1536.f);
  }
  __syncthreads();
  float mu=smean[tt];
  float s2=0.f;
  #pragma unroll
  for(int j=0;j<32;j++){ float dd=Cs[tt*1536+sub+48*j]-mu; s2=fmaf(dd,dd,s2); }
  sred[tid]=s2;
  __syncthreads();
  if(w<8){
    float v=sred[w*48+lane]+((lane<16)? sred[w*48+32+lane] : 0.f);
    for(int off=16;off;off>>=1) v+=__shfl_xor_sync(0xffffffffu,v,off);
    if(lane==0) srstd[w]=rsqrtf(v*(1.f/1536.f)+1e-5f);
  }
  __syncthreads();
  for(int f=tid; f<12288; f+=384){
    int tk=f/1536, e=f%1536;
    out[rowBase*128 + f] = (Cs[f]-smean[tk])*srstd[tk]*gamma[e]+beta[e];
  }
}

extern "C" void kernel_launch(void* const* d_in, const int* in_sizes, int n_in,
                              void* d_out, int out_size){
  const float* x     =(const float*)d_in[0];
  const float* conv_w=(const float*)d_in[1];
  const float* conv_b=(const float*)d_in[2];
  const float* cemb  =(const float*)d_in[3];
  const float* cq    =(const float*)d_in[4];
  const float* gw    =(const float*)d_in[5];
  const float* gb    =(const float*)d_in[6];
  const float* gow   =(const float*)d_in[7];
  const float* gob   =(const float*)d_in[8];
  const float* eq    =(const float*)d_in[9];
  const float* ew    =(const float*)d_in[10];
  const float* eb    =(const float*)d_in[11];
  const float* eow   =(const float*)d_in[12];
  const float* eob   =(const float*)d_in[13];
  const float* gamma =(const float*)d_in[14];
  const float* beta  =(const float*)d_in[15];
  float* out=(float*)d_out;

  cudaFuncSetAttribute(k_main,    cudaFuncAttributeMaxDynamicSharedMemorySize, 54864);
  cudaFuncSetAttribute(k_hmma_ln, cudaFuncAttributeMaxDynamicSharedMemorySize, 121856);

  k_setupA<<<1717,256>>>(conv_b,cemb,cq,gw,gb,gow,gob,eq,ew,eb,eow,eob);
  k_coef<<<24,128>>>(gw,gb,conv_w);
  k_misc<<<656,256>>>(conv_w,ew,eb);
  k_main<<<512,256,54864>>>(x);
  k_ens1<<<8192,256>>>();
  k_hmma_ln<<<1024,384,121856>>>(gamma,beta,out);
}

// round 15
// speedup vs baseline: 1.0266x; 1.0266x over previous
#include <cuda_runtime.h>
#include <cuda_bf16.h>
#include <cstdint>

#define NCC 68
#define SCALEF 0.125f

// ---------------- device scratch ----------------
__device__ float g_cbe[NCC*128];
__device__ float g_qg[12*128];
__device__ float g_qe[12*128];
__device__ float g_pe[24*128];
__device__ float g_cKe[24];
__device__ float g_MTg[12*2*128*128];
__device__ float g_cg[12*128];
__device__ float g_MTe[2*128*128];
__device__ float g_ce[128];
__device__ float g_coef2[206*5];
__device__ int   g_mm_cc[206];
__device__ float g_T[206*5*128];
__device__ float g_xbar[8192*12*256];
__device__ float g_r[8192*12*128];
__device__ unsigned short g_Bh2[128*256];
__device__ unsigned short g_Bl2[128*256];

__device__ __forceinline__ int grp_n(int i){ return i<5?7:(i<10?9:(i==10?17:6)); }
__device__ __forceinline__ int grp_s(int i){ return 2*(i<5? 7*i : (i<10? 35+9*(i-5) : (i==10? 80 : 97))); }
__device__ __forceinline__ int grp_off(int i){ int m=i%5; return m==0?3:(m==1?4:(m==2?2:(m==3?1:0))); }
__device__ __forceinline__ int member_cc(int i,int j){ return i<10 ? 5*j+grp_off(i) : (i==10?45+j:62+j); }
__device__ __forceinline__ int orig_ch(int cc){ return cc<45?cc:cc+20; }
__device__ __forceinline__ void m_decode(int m,int&ih,int&g,int&cc){
  for(int i=0;i<12;i++){ int n=grp_n(i); if(m<2*n){ int h=m/n; g=m%n; ih=2*i+h; cc=member_cc(i,g); return;} m-=2*n; }
  ih=0;g=0;cc=0;
}

// ---------------- setup A ----------------
__global__ void k_setupA(const float* __restrict__ cb,const float* __restrict__ cemb,
    const float* __restrict__ cq,const float* __restrict__ gw,const float* __restrict__ gb,
    const float* __restrict__ gow,const float* __restrict__ gob,const float* __restrict__ eq,
    const float* __restrict__ ew,const float* __restrict__ eb,const float* __restrict__ eow,
    const float* __restrict__ eob){
  int idx = blockIdx.x*256+threadIdx.x;
  if(idx<8704){ int cc=idx>>7,d=idx&127,c=orig_ch(cc); g_cbe[idx]=cb[c*128+d]+cemb[c*128+d]; return;}
  idx-=8704;
  if(idx<1536){ int i=idx>>7,r=idx&127; float s=gb[i*384+r];
    const float* w=gw+(i*384+r)*128; const float* q=cq+i*128;
    for(int d=0;d<128;d++) s=fmaf(q[d],w[d],s); g_qg[i*128+r]=s; return;}
  idx-=1536;
  if(idx<1536){ int t=idx>>7,r=idx&127; float s=eb[r];
    const float* w=ew+r*128; const float* q=eq+t*128;
    for(int d=0;d<128;d++) s=fmaf(q[d],w[d],s); g_qe[t*128+r]=s; return;}
  idx-=1536;
  if(idx<393216){ int i=idx>>15, rem=idx&32767, h=rem>>14, dout=(rem>>7)&127, k=rem&127;
    float s=0.f; const float* gr=gow+i*16384+dout*128+h*64;
    for(int e=0;e<64;e++) s=fmaf(gr[e], gw[(i*384+256+h*64+e)*128+k], s);
    g_MTg[((i*2+h)*128+k)*128+dout]=s; return;}
  idx-=393216;
  if(idx<1536){ int i=idx>>7,dout=idx&127; float s=gob[i*128+dout];
    const float* gr=gow+i*16384+dout*128;
    for(int r=0;r<128;r++) s=fmaf(gr[r], gb[i*384+256+r], s); g_cg[idx]=s; return;}
  idx-=1536;
  if(idx<32768){ int h=idx>>14, dout=(idx>>7)&127, k=idx&127;
    float s=0.f; const float* er=eow+dout*128+h*64;
    for(int e=0;e<64;e++) s=fmaf(er[e], ew[(256+h*64+e)*128+k], s);
    g_MTe[(h*128+k)*128+dout]=s; return;}
  idx-=32768;
  if(idx<128){ float s=eob[idx]; const float* er=eow+idx*128;
    for(int r=0;r<128;r++) s=fmaf(er[r], eb[256+r], s); g_ce[idx]=s;}
}

// ---------------- merged setup: misc (blocks 0..655) + coef (blocks 656..679) ----------------
__global__ void k_cm(const float* __restrict__ conv_w,const float* __restrict__ ew,
                     const float* __restrict__ eb,const float* __restrict__ gw,
                     const float* __restrict__ gb){
  if(blockIdx.x<656){
    int idx=blockIdx.x*256+threadIdx.x;
    if(idx<131840){
      int m=idx/640, p=(idx/128)%5, dout=idx&127;
      int ih,g,cc; m_decode(m,ih,g,cc);
      const float* M=g_MTg+ih*16384;
      float s=0.f;
      if(p<4){ const float* w=conv_w+(orig_ch(cc)*4+p)*128;
        for(int k=0;k<128;k++) s=fmaf(w[k], M[k*128+dout], s);
      } else { const float* w=g_cbe+cc*128;
        for(int k=0;k<128;k++) s=fmaf(w[k], M[k*128+dout], s);
      }
      g_T[idx]=s; return;
    }
    idx-=131840;
    if(idx<32768){
      int n=idx>>8, k=idx&255;
      float v=g_MTe[k*128+n];
      uint32_t hp; asm("cvt.rn.bf16x2.f32 %0,%1,%2;" : "=r"(hp) : "f"(0.f), "f"(v));
      float vh=__uint_as_float(hp<<16);
      float lo=v-vh;
      uint32_t lp; asm("cvt.rn.bf16x2.f32 %0,%1,%2;" : "=r"(lp) : "f"(0.f), "f"(lo));
      g_Bh2[n*256+k]=(unsigned short)(hp&0xffffu);
      g_Bl2[n*256+k]=(unsigned short)(lp&0xffffu);
      return;
    }
    idx-=32768;
    if(idx<3072){
      int th=idx>>7,d=idx&127,t=th>>1,h=th&1;
      float s=0.f; const float* q=g_qe+t*128+h*64;
      for(int e=0;e<64;e++) s=fmaf(q[e], ew[(128+h*64+e)*128+d], s);
      g_pe[idx]=s*SCALEF; return;
    }
    idx-=3072;
    if(idx<24){
      int t=idx>>1,h=idx&1; float s=0.f; const float* q=g_qe+t*128+h*64;
      for(int e=0;e<64;e++) s=fmaf(q[e], eb[128+h*64+e], s);
      g_cKe[idx]=s*SCALEF;
    }
    return;
  }
  // coef path: one block per ih; tid<128 active, all 256 reach syncthreads
  __shared__ float sred[4];
  int ih=blockIdx.x-656, i=ih>>1, h=ih&1, d=threadIdx.x;
  bool act = d<128;
  const float* q=g_qg+i*128+h*64;
  float pv=0.f, ck=0.f;
  if(act){
    for(int e=0;e<64;e++) pv=fmaf(q[e], gw[(i*384+128+h*64+e)*128+d], pv);
    pv*=SCALEF;
    for(int e=0;e<64;e++) ck=fmaf(q[e], gb[i*384+128+h*64+e], ck);
    ck*=SCALEF;
  }
  int n=grp_n(i), ms=grp_s(i)+h*n;
  for(int g=0;g<n;g++){
    int cc=member_cc(i,g);
    for(int p=0;p<5;p++){
      if(act){
        float w = (p<4)? conv_w[(orig_ch(cc)*4+p)*128+d] : g_cbe[cc*128+d];
        float v = pv*w;
        for(int off=16;off;off>>=1) v+=__shfl_xor_sync(0xffffffffu,v,off);
        if((d&31)==0) sred[d>>5]=v;
      }
      __syncthreads();
      if(d==0){
        float s=sred[0]+sred[1]+sred[2]+sred[3];
        if(p==4) s+=ck;
        g_coef2[(ms+g)*5+p]=s;
        g_mm_cc[ms+g]=cc;
      }
      __syncthreads();
    }
  }
}

// ---------------- K-main: r12 form (32 tokens/CTA + head-paired patch reuse) ----------------
__global__ void __launch_bounds__(256,3) k_main(const float* __restrict__ x){
  extern __shared__ float sm[];
  float* sp  = sm;             // 8704
  float* sa  = sm + 8704;      // 6592
  float* scf = sm + 15296;     // 1030
  int*   scc = (int*)(sm + 16326); // 206
  int tid=threadIdx.x;
  int hp = blockIdx.x>>2, wb = blockIdx.x&3;
  for(int f=tid; f<8704; f+=256){
    int cc=f>>7, r=f&127, pi=r>>6, j=r&63, t=j>>1, pj=j&1;
    sp[(cc*4+pi*2+pj)*32+t] = x[orig_ch(cc)*32768 + (2*hp+pi)*256 + wb*64 + j];
  }
  for(int f=tid; f<1030; f+=256) scf[f]=g_coef2[f];
  if(tid<206) scc[tid]=g_mm_cc[tid];
  __syncthreads();
  for(int f=tid; f<6592; f+=256){
    int m=f>>5, t=f&31;
    const float* cf=scf+m*5;
    const float* pb=sp+scc[m]*128;
    sa[f]=fmaf(cf[0],pb[t],fmaf(cf[1],pb[32+t],fmaf(cf[2],pb[64+t],fmaf(cf[3],pb[96+t],cf[4]))));
  }
  __syncthreads();
  for(int f=tid; f<768; f+=256){
    int j=f>>5, t=f&31, i=j>>1, h=j&1;
    int n=grp_n(i), st=grp_s(i)+h*n;
    float mx=-1e30f;
    for(int g=0;g<n;g++) mx=fmaxf(mx, sa[(st+g)*32+t]);
    float sum=0.f;
    for(int g=0;g<n;g++){ float e=__expf(sa[(st+g)*32+t]-mx); sa[(st+g)*32+t]=e; sum+=e; }
    float inv=1.f/sum;
    for(int g=0;g<n;g++) sa[(st+g)*32+t]*=inv;
  }
  __syncthreads();
  int d=tid&127, th=tid>>7;
  int l0=blockIdx.x*32 + th*16;
  for(int i=0;i<12;i++){
    float acc[16];
    float bias=g_cg[i*128+d];
    #pragma unroll
    for(int t=0;t<16;t++) acc[t]=bias;
    int st=grp_s(i), n=grp_n(i);
    for(int g=0;g<n;g++){
      int m0=st+g, m1=m0+n;
      const float* Ta=g_T+m0*640+d;
      const float* Tb=g_T+m1*640+d;
      float A0=Ta[0],A1=Ta[128],A2=Ta[256],A3=Ta[384],A4=Ta[512];
      float B0=Tb[0],B1=Tb[128],B2=Tb[256],B3=Tb[384],B4=Tb[512];
      const float* pb=sp+scc[m0]*128+th*16;
      const float* aa=sa+m0*32+th*16;
      const float* ab=sa+m1*32+th*16;
      #pragma unroll
      for(int q=0;q<4;q++){
        float4 p0=*(const float4*)(pb+q*4);
        float4 p1=*(const float4*)(pb+32+q*4);
        float4 p2=*(const float4*)(pb+64+q*4);
        float4 p3=*(const float4*)(pb+96+q*4);
        float4 av0=*(const float4*)(aa+q*4);
        float4 av1=*(const float4*)(ab+q*4);
        float ia,ib;
        ia=fmaf(A0,p0.x,fmaf(A1,p1.x,fmaf(A2,p2.x,fmaf(A3,p3.x,A4))));
        ib=fmaf(B0,p0.x,fmaf(B1,p1.x,fmaf(B2,p2.x,fmaf(B3,p3.x,B4))));
        acc[q*4+0]=fmaf(av0.x,ia,fmaf(av1.x,ib,acc[q*4+0]));
        ia=fmaf(A0,p0.y,fmaf(A1,p1.y,fmaf(A2,p2.y,fmaf(A3,p3.y,A4))));
        ib=fmaf(B0,p0.y,fmaf(B1,p1.y,fmaf(B2,p2.y,fmaf(B3,p3.y,B4))));
        acc[q*4+1]=fmaf(av0.y,ia,fmaf(av1.y,ib,acc[q*4+1]));
        ia=fmaf(A0,p0.z,fmaf(A1,p1.z,fmaf(A2,p2.z,fmaf(A3,p3.z,A4))));
        ib=fmaf(B0,p0.z,fmaf(B1,p1.z,fmaf(B2,p2.z,fmaf(B3,p3.z,B4))));
        acc[q*4+2]=fmaf(av0.z,ia,fmaf(av1.z,ib,acc[q*4+2]));
        ia=fmaf(A0,p0.w,fmaf(A1,p1.w,fmaf(A2,p2.w,fmaf(A3,p3.w,A4))));
        ib=fmaf(B0,p0.w,fmaf(B1,p1.w,fmaf(B2,p2.w,fmaf(B3,p3.w,B4))));
        acc[q*4+3]=fmaf(av0.w,ia,fmaf(av1.w,ib,acc[q*4+3]));
      }
    }
    #pragma unroll
    for(int t=0;t<16;t++)
      g_r[((l0+t)*12+i)*128+d]=acc[t];
  }
}

// ---------------- ensemble scores + obar (launch #4 -> gets profiled) ----------------
__global__ void k_ens1(){
  __shared__ float sout[1536];
  __shared__ float ssc[288];
  int tid=threadIdx.x, lane=tid&31, wid=tid>>5;
  int l=blockIdx.x;
  for(int f=tid; f<1536; f+=256) sout[f]=g_r[l*1536+f];
  __syncthreads();
  for(int dot=wid; dot<288; dot+=8){
    int th=dot/12, s=dot%12;
    const float* p=g_pe+th*128;
    const float* o=sout+s*128;
    float v=0.f;
    #pragma unroll
    for(int q=0;q<4;q++){ int dd=lane+32*q; v=fmaf(p[dd],o[dd],v); }
    for(int off=16;off;off>>=1) v+=__shfl_xor_sync(0xffffffffu,v,off);
    if(lane==0) ssc[dot]=v+g_cKe[th];
  }
  __syncthreads();
  if(tid<24){
    float* s=ssc+tid*12;
    float mx=-1e30f; for(int j=0;j<12;j++) mx=fmaxf(mx,s[j]);
    float sum=0.f; for(int j=0;j<12;j++){ float e=__expf(s[j]-mx); s[j]=e; sum+=e; }
    float inv=1.f/sum; for(int j=0;j<12;j++) s[j]*=inv;
  }
  __syncthreads();
  for(int o=tid;o<3072;o+=256){
    int d=o&127, th=o>>7;
    const float* w=ssc+th*12;
    float acc=0.f;
    #pragma unroll
    for(int s=0;s<12;s++) acc=fmaf(w[s], sout[s*128+d], acc);
    g_xbar[l*3072+th*128+d]=acc;
  }
}

// ---------------- HMMA GEMM + LayerNorm: 96 rows (8 tokens)/CTA ----------------
#define SPITCH 136
__global__ void __launch_bounds__(384,1) k_hmma_ln(const float* __restrict__ gamma,
    const float* __restrict__ beta, float* __restrict__ out){
  extern __shared__ unsigned short smu16[];
  unsigned short* Ah = smu16;
  unsigned short* Al = Ah + 96*SPITCH;
  unsigned short* Bh = Al + 96*SPITCH;
  unsigned short* Bl = Bh + 128*SPITCH;
  float* Cs = (float*)smu16;
  __shared__ float sred[384];
  __shared__ float smean[8], srstd[8];
  int tid=threadIdx.x, w=tid>>5, lane=tid&31;
  int mw=w>>2, nw=w&3, g=lane>>2, t=lane&3;
  size_t rowBase=(size_t)blockIdx.x*96;
  float c[2][4][4];
  #pragma unroll
  for(int mi=0;mi<2;mi++)
    #pragma unroll
    for(int ni=0;ni<4;ni++){ c[mi][ni][0]=0.f;c[mi][ni][1]=0.f;c[mi][ni][2]=0.f;c[mi][ni][3]=0.f; }

  for(int chunk=0; chunk<2; chunk++){
    if(chunk) __syncthreads();
    for(int f=tid; f<3072; f+=384){
      int row=f>>5, kq=f&31;
      float4 v=*(const float4*)(g_xbar + (rowBase+row)*256 + chunk*128 + kq*4);
      uint32_t h01,h23,l01,l23;
      asm("cvt.rn.bf16x2.f32 %0,%1,%2;" : "=r"(h01) : "f"(v.y), "f"(v.x));
      asm("cvt.rn.bf16x2.f32 %0,%1,%2;" : "=r"(h23) : "f"(v.w), "f"(v.z));
      float hx=__uint_as_float(h01<<16), hy=__uint_as_float(h01&0xffff0000u);
      float hz=__uint_as_float(h23<<16), hw=__uint_as_float(h23&0xffff0000u);
      asm("cvt.rn.bf16x2.f32 %0,%1,%2;" : "=r"(l01) : "f"(v.y-hy), "f"(v.x-hx));
      asm("cvt.rn.bf16x2.f32 %0,%1,%2;" : "=r"(l23) : "f"(v.w-hw), "f"(v.z-hz));
      uint32_t off=row*SPITCH + kq*4;
      *(uint32_t*)(Ah+off)=h01; *(uint32_t*)(Ah+off+2)=h23;
      *(uint32_t*)(Al+off)=l01; *(uint32_t*)(Al+off+2)=l23;
    }
    for(int f=tid; f<8192; f+=384){
      int n=f>>6, kp=(f&63)*2;
      *(uint32_t*)(Bh+n*SPITCH+kp)=*(const uint32_t*)(g_Bh2+n*256+chunk*128+kp);
      *(uint32_t*)(Bl+n*SPITCH+kp)=*(const uint32_t*)(g_Bl2+n*256+chunk*128+kp);
    }
    __syncthreads();
    #pragma unroll
    for(int prod=0; prod<3; prod++){
      const unsigned short* As = (prod<2)? Ah : Al;
      const unsigned short* Bs = (prod==1)? Bl : Bh;
      #pragma unroll
      for(int ks=0; ks<8; ks++){
        int kb = ks*16;
        uint32_t a[2][4];
        #pragma unroll
        for(int mi=0;mi<2;mi++){
          int r0 = mw*32 + mi*16;
          a[mi][0]=*(const uint32_t*)(As+(r0+g  )*SPITCH + kb + 2*t);
          a[mi][1]=*(const uint32_t*)(As+(r0+g+8)*SPITCH + kb + 2*t);
          a[mi][2]=*(const uint32_t*)(As+(r0+g  )*SPITCH + kb + 8 + 2*t);
          a[mi][3]=*(const uint32_t*)(As+(r0+g+8)*SPITCH + kb + 8 + 2*t);
        }
        uint32_t b[4][2];
        #pragma unroll
        for(int ni=0;ni<4;ni++){
          int n0 = nw*32 + ni*8 + g;
          b[ni][0]=*(const uint32_t*)(Bs+n0*SPITCH + kb + 2*t);
          b[ni][1]=*(const uint32_t*)(Bs+n0*SPITCH + kb + 8 + 2*t);
        }
        #pragma unroll
        for(int mi=0;mi<2;mi++)
          #pragma unroll
          for(int ni=0;ni<4;ni++){
            asm volatile("mma.sync.aligned.m16n8k16.row.col.f32.bf16.bf16.f32 "
              "{%0,%1,%2,%3},{%4,%5,%6,%7},{%8,%9},{%0,%1,%2,%3};"
              : "+f"(c[mi][ni][0]),"+f"(c[mi][ni][1]),"+f"(c[mi][ni][2]),"+f"(c[mi][ni][3])
              : "r"(a[mi][0]),"r"(a[mi][1]),"r"(a[mi][2]),"r"(a[mi][3]),
                "r"(b[ni][0]),"r"(b[ni][1]));
          }
      }
    }
  }
  __syncthreads();
  #pragma unroll
  for(int mi=0;mi<2;mi++){
    #pragma unroll
    for(int ni=0;ni<4;ni++){
      int col = nw*32 + ni*8 + 2*t;
      float bi0=g_ce[col], bi1=g_ce[col+1];
      int r0 = mw*32 + mi*16 + g;
      Cs[r0*128+col]    =c[mi][ni][0]+bi0; Cs[r0*128+col+1]    =c[mi][ni][1]+bi1;
      Cs[(r0+8)*128+col]=c[mi][ni][2]+bi0; Cs[(r0+8)*128+col+1]=c[mi][ni][3]+bi1;
    }
  }
  __syncthreads();
  int tt=tid/48, sub=tid%48;
  float s1=0.f;
  #pragma unroll
  for(int j=0;j<32;j++) s1+=Cs[tt*1536+sub+48*j];
  sred[tid]=s1;
  __syncthreads();
  if(w<8){
    float v=sred[w*48+lane]+((lane<16)? sred[w*48+32+lane] : 0.f);
    for(int off=16;off;off>>=1) v+=__shfl_xor_sync(0xffffffffu,v,off);
    if(lane==0) smean[w]=v*(1.f/1536.f);
  }
  __syncthreads();
  float mu=smean[tt];
  float s2=0.f;
  #pragma unroll
  for(int j=0;j<32;j++){ float dd=Cs[tt*1536+sub+48*j]-mu; s2=fmaf(dd,dd,s2); }
  sred[tid]=s2;
  __syncthreads();
  if(w<8){
    float v=sred[w*48+lane]+((lane<16)? sred[w*48+32+lane] : 0.f);
    for(int off=16;off;off>>=1) v+=__shfl_xor_sync(0xffffffffu,v,off);
    if(lane==0) srstd[w]=rsqrtf(v*(1.f/1536.f)+1e-5f);
  }
  __syncthreads();
  for(int f=tid; f<12288; f+=384){
    int tk=f/1536, e=f%1536;
    out[rowBase*128 + f] = (Cs[f]-smean[tk])*srstd[tk]*gamma[e]+beta[e];
  }
}

extern "C" void kernel_launch(void* const* d_in, const int* in_sizes, int n_in,
                              void* d_out, int out_size){
  const float* x     =(const float*)d_in[0];
  const float* conv_w=(const float*)d_in[1];
  const float* conv_b=(const float*)d_in[2];
  const float* cemb  =(const float*)d_in[3];
  const float* cq    =(const float*)d_in[4];
  const float* gw    =(const float*)d_in[5];
  const float* gb    =(const float*)d_in[6];
  const float* gow   =(const float*)d_in[7];
  const float* gob   =(const float*)d_in[8];
  const float* eq    =(const float*)d_in[9];
  const float* ew    =(const float*)d_in[10];
  const float* eb    =(const float*)d_in[11];
  const float* eow   =(const float*)d_in[12];
  const float* eob   =(const float*)d_in[13];
  const float* gamma =(const float*)d_in[14];
  const float* beta  =(const float*)d_in[15];
  float* out=(float*)d_out;

  cudaFuncSetAttribute(k_main,    cudaFuncAttributeMaxDynamicSharedMemorySize, 66128);
  cudaFuncSetAttribute(k_hmma_ln, cudaFuncAttributeMaxDynamicSharedMemorySize, 121856);

  k_setupA<<<1717,256>>>(conv_b,cemb,cq,gw,gb,gow,gob,eq,ew,eb,eow,eob);
  k_cm<<<680,256>>>(conv_w,ew,eb,gw,gb);
  k_main<<<256,256,66128>>>(x);
  k_ens1<<<8192,256>>>();
  k_hmma_ln<<<1024,384,121856>>>(gamma,beta,out);
}

// round 16
// speedup vs baseline: 1.0972x; 1.0688x over previous
#include <cuda_runtime.h>
#include <cuda_bf16.h>
#include <cstdint>

#define NCC 68
#define SCALEF 0.125f

// ---------------- device scratch ----------------
__device__ float g_cbe[NCC*128];
__device__ float g_qg[12*128];
__device__ float g_qe[12*128];
__device__ float g_pe[24*128];
__device__ float g_cKe[24];
__device__ float g_MTg[12*2*128*128];
__device__ float g_cg[12*128];
__device__ float g_MTe[2*128*128];
__device__ float g_ce[128];
__device__ float g_coef2[206*5];
__device__ int   g_mm_cc[206];
__device__ float g_T[206*5*128];
__device__ float g_xbar[8192*12*256];
__device__ float g_r[8192*12*128];
__device__ unsigned short g_Bh2[128*256];
__device__ unsigned short g_Bl2[128*256];

__device__ __forceinline__ int grp_n(int i){ return i<5?7:(i<10?9:(i==10?17:6)); }
__device__ __forceinline__ int grp_s(int i){ return 2*(i<5? 7*i : (i<10? 35+9*(i-5) : (i==10? 80 : 97))); }
__device__ __forceinline__ int grp_off(int i){ int m=i%5; return m==0?3:(m==1?4:(m==2?2:(m==3?1:0))); }
__device__ __forceinline__ int member_cc(int i,int j){ return i<10 ? 5*j+grp_off(i) : (i==10?45+j:62+j); }
__device__ __forceinline__ int orig_ch(int cc){ return cc<45?cc:cc+20; }
__device__ __forceinline__ void m_decode(int m,int&ih,int&g,int&cc){
  for(int i=0;i<12;i++){ int n=grp_n(i); if(m<2*n){ int h=m/n; g=m%n; ih=2*i+h; cc=member_cc(i,g); return;} m-=2*n; }
  ih=0;g=0;cc=0;
}

// ---------------- setup A ----------------
__global__ void k_setupA(const float* __restrict__ cb,const float* __restrict__ cemb,
    const float* __restrict__ cq,const float* __restrict__ gw,const float* __restrict__ gb,
    const float* __restrict__ gow,const float* __restrict__ gob,const float* __restrict__ eq,
    const float* __restrict__ ew,const float* __restrict__ eb,const float* __restrict__ eow,
    const float* __restrict__ eob){
  int idx = blockIdx.x*256+threadIdx.x;
  if(idx<8704){ int cc=idx>>7,d=idx&127,c=orig_ch(cc); g_cbe[idx]=cb[c*128+d]+cemb[c*128+d]; return;}
  idx-=8704;
  if(idx<1536){ int i=idx>>7,r=idx&127; float s=gb[i*384+r];
    const float* w=gw+(i*384+r)*128; const float* q=cq+i*128;
    for(int d=0;d<128;d++) s=fmaf(q[d],w[d],s); g_qg[i*128+r]=s; return;}
  idx-=1536;
  if(idx<1536){ int t=idx>>7,r=idx&127; float s=eb[r];
    const float* w=ew+r*128; const float* q=eq+t*128;
    for(int d=0;d<128;d++) s=fmaf(q[d],w[d],s); g_qe[t*128+r]=s; return;}
  idx-=1536;
  if(idx<393216){ int i=idx>>15, rem=idx&32767, h=rem>>14, dout=(rem>>7)&127, k=rem&127;
    float s=0.f; const float* gr=gow+i*16384+dout*128+h*64;
    for(int e=0;e<64;e++) s=fmaf(gr[e], gw[(i*384+256+h*64+e)*128+k], s);
    g_MTg[((i*2+h)*128+k)*128+dout]=s; return;}
  idx-=393216;
  if(idx<1536){ int i=idx>>7,dout=idx&127; float s=gob[i*128+dout];
    const float* gr=gow+i*16384+dout*128;
    for(int r=0;r<128;r++) s=fmaf(gr[r], gb[i*384+256+r], s); g_cg[idx]=s; return;}
  idx-=1536;
  if(idx<32768){ int h=idx>>14, dout=(idx>>7)&127, k=idx&127;
    float s=0.f; const float* er=eow+dout*128+h*64;
    for(int e=0;e<64;e++) s=fmaf(er[e], ew[(256+h*64+e)*128+k], s);
    g_MTe[(h*128+k)*128+dout]=s; return;}
  idx-=32768;
  if(idx<128){ float s=eob[idx]; const float* er=eow+idx*128;
    for(int r=0;r<128;r++) s=fmaf(er[r], eb[256+r], s); g_ce[idx]=s;}
}

// ---------------- merged setup: misc (blocks 0..655) + coef (blocks 656..679) ----------------
__global__ void k_cm(const float* __restrict__ conv_w,const float* __restrict__ ew,
                     const float* __restrict__ eb,const float* __restrict__ gw,
                     const float* __restrict__ gb){
  if(blockIdx.x<656){
    int idx=blockIdx.x*256+threadIdx.x;
    if(idx<131840){
      int m=idx/640, p=(idx/128)%5, dout=idx&127;
      int ih,g,cc; m_decode(m,ih,g,cc);
      const float* M=g_MTg+ih*16384;
      float s=0.f;
      if(p<4){ const float* w=conv_w+(orig_ch(cc)*4+p)*128;
        for(int k=0;k<128;k++) s=fmaf(w[k], M[k*128+dout], s);
      } else { const float* w=g_cbe+cc*128;
        for(int k=0;k<128;k++) s=fmaf(w[k], M[k*128+dout], s);
      }
      g_T[idx]=s; return;
    }
    idx-=131840;
    if(idx<32768){
      int n=idx>>8, k=idx&255;
      float v=g_MTe[k*128+n];
      uint32_t hp; asm("cvt.rn.bf16x2.f32 %0,%1,%2;" : "=r"(hp) : "f"(0.f), "f"(v));
      float vh=__uint_as_float(hp<<16);
      float lo=v-vh;
      uint32_t lp; asm("cvt.rn.bf16x2.f32 %0,%1,%2;" : "=r"(lp) : "f"(0.f), "f"(lo));
      g_Bh2[n*256+k]=(unsigned short)(hp&0xffffu);
      g_Bl2[n*256+k]=(unsigned short)(lp&0xffffu);
      return;
    }
    idx-=32768;
    if(idx<3072){
      int th=idx>>7,d=idx&127,t=th>>1,h=th&1;
      float s=0.f; const float* q=g_qe+t*128+h*64;
      for(int e=0;e<64;e++) s=fmaf(q[e], ew[(128+h*64+e)*128+d], s);
      g_pe[idx]=s*SCALEF; return;
    }
    idx-=3072;
    if(idx<24){
      int t=idx>>1,h=idx&1; float s=0.f; const float* q=g_qe+t*128+h*64;
      for(int e=0;e<64;e++) s=fmaf(q[e], eb[128+h*64+e], s);
      g_cKe[idx]=s*SCALEF;
    }
    return;
  }
  __shared__ float sred[4];
  int ih=blockIdx.x-656, i=ih>>1, h=ih&1, d=threadIdx.x;
  bool act = d<128;
  const float* q=g_qg+i*128+h*64;
  float pv=0.f, ck=0.f;
  if(act){
    for(int e=0;e<64;e++) pv=fmaf(q[e], gw[(i*384+128+h*64+e)*128+d], pv);
    pv*=SCALEF;
    for(int e=0;e<64;e++) ck=fmaf(q[e], gb[i*384+128+h*64+e], ck);
    ck*=SCALEF;
  }
  int n=grp_n(i), ms=grp_s(i)+h*n;
  for(int g=0;g<n;g++){
    int cc=member_cc(i,g);
    for(int p=0;p<5;p++){
      if(act){
        float w = (p<4)? conv_w[(orig_ch(cc)*4+p)*128+d] : g_cbe[cc*128+d];
        float v = pv*w;
        for(int off=16;off;off>>=1) v+=__shfl_xor_sync(0xffffffffu,v,off);
        if((d&31)==0) sred[d>>5]=v;
      }
      __syncthreads();
      if(d==0){
        float s=sred[0]+sred[1]+sred[2]+sred[3];
        if(p==4) s+=ck;
        g_coef2[(ms+g)*5+p]=s;
        g_mm_cc[ms+g]=cc;
      }
      __syncthreads();
    }
  }
}

// ---------------- K-main: r12 form ----------------
__global__ void __launch_bounds__(256,3) k_main(const float* __restrict__ x){
  extern __shared__ float sm[];
  float* sp  = sm;             // 8704
  float* sa  = sm + 8704;      // 6592
  float* scf = sm + 15296;     // 1030
  int*   scc = (int*)(sm + 16326); // 206
  int tid=threadIdx.x;
  int hp = blockIdx.x>>2, wb = blockIdx.x&3;
  for(int f=tid; f<8704; f+=256){
    int cc=f>>7, r=f&127, pi=r>>6, j=r&63, t=j>>1, pj=j&1;
    sp[(cc*4+pi*2+pj)*32+t] = x[orig_ch(cc)*32768 + (2*hp+pi)*256 + wb*64 + j];
  }
  for(int f=tid; f<1030; f+=256) scf[f]=g_coef2[f];
  if(tid<206) scc[tid]=g_mm_cc[tid];
  __syncthreads();
  for(int f=tid; f<6592; f+=256){
    int m=f>>5, t=f&31;
    const float* cf=scf+m*5;
    const float* pb=sp+scc[m]*128;
    sa[f]=fmaf(cf[0],pb[t],fmaf(cf[1],pb[32+t],fmaf(cf[2],pb[64+t],fmaf(cf[3],pb[96+t],cf[4]))));
  }
  __syncthreads();
  for(int f=tid; f<768; f+=256){
    int j=f>>5, t=f&31, i=j>>1, h=j&1;
    int n=grp_n(i), st=grp_s(i)+h*n;
    float mx=-1e30f;
    for(int g=0;g<n;g++) mx=fmaxf(mx, sa[(st+g)*32+t]);
    float sum=0.f;
    for(int g=0;g<n;g++){ float e=__expf(sa[(st+g)*32+t]-mx); sa[(st+g)*32+t]=e; sum+=e; }
    float inv=1.f/sum;
    for(int g=0;g<n;g++) sa[(st+g)*32+t]*=inv;
  }
  __syncthreads();
  int d=tid&127, th=tid>>7;
  int l0=blockIdx.x*32 + th*16;
  for(int i=0;i<12;i++){
    float acc[16];
    float bias=g_cg[i*128+d];
    #pragma unroll
    for(int t=0;t<16;t++) acc[t]=bias;
    int st=grp_s(i), n=grp_n(i);
    for(int g=0;g<n;g++){
      int m0=st+g, m1=m0+n;
      const float* Ta=g_T+m0*640+d;
      const float* Tb=g_T+m1*640+d;
      float A0=Ta[0],A1=Ta[128],A2=Ta[256],A3=Ta[384],A4=Ta[512];
      float B0=Tb[0],B1=Tb[128],B2=Tb[256],B3=Tb[384],B4=Tb[512];
      const float* pb=sp+scc[m0]*128+th*16;
      const float* aa=sa+m0*32+th*16;
      const float* ab=sa+m1*32+th*16;
      #pragma unroll
      for(int q=0;q<4;q++){
        float4 p0=*(const float4*)(pb+q*4);
        float4 p1=*(const float4*)(pb+32+q*4);
        float4 p2=*(const float4*)(pb+64+q*4);
        float4 p3=*(const float4*)(pb+96+q*4);
        float4 av0=*(const float4*)(aa+q*4);
        float4 av1=*(const float4*)(ab+q*4);
        float ia,ib;
        ia=fmaf(A0,p0.x,fmaf(A1,p1.x,fmaf(A2,p2.x,fmaf(A3,p3.x,A4))));
        ib=fmaf(B0,p0.x,fmaf(B1,p1.x,fmaf(B2,p2.x,fmaf(B3,p3.x,B4))));
        acc[q*4+0]=fmaf(av0.x,ia,fmaf(av1.x,ib,acc[q*4+0]));
        ia=fmaf(A0,p0.y,fmaf(A1,p1.y,fmaf(A2,p2.y,fmaf(A3,p3.y,A4))));
        ib=fmaf(B0,p0.y,fmaf(B1,p1.y,fmaf(B2,p2.y,fmaf(B3,p3.y,B4))));
        acc[q*4+1]=fmaf(av0.y,ia,fmaf(av1.y,ib,acc[q*4+1]));
        ia=fmaf(A0,p0.z,fmaf(A1,p1.z,fmaf(A2,p2.z,fmaf(A3,p3.z,A4))));
        ib=fmaf(B0,p0.z,fmaf(B1,p1.z,fmaf(B2,p2.z,fmaf(B3,p3.z,B4))));
        acc[q*4+2]=fmaf(av0.z,ia,fmaf(av1.z,ib,acc[q*4+2]));
        ia=fmaf(A0,p0.w,fmaf(A1,p1.w,fmaf(A2,p2.w,fmaf(A3,p3.w,A4))));
        ib=fmaf(B0,p0.w,fmaf(B1,p1.w,fmaf(B2,p2.w,fmaf(B3,p3.w,B4))));
        acc[q*4+3]=fmaf(av0.w,ia,fmaf(av1.w,ib,acc[q*4+3]));
      }
    }
    #pragma unroll
    for(int t=0;t<16;t++)
      g_r[((l0+t)*12+i)*128+d]=acc[t];
  }
}

// ---------------- ensemble scores + obar (rewritten: no div/mod, s-outer obar) ----------------
__global__ void __launch_bounds__(256,4) k_ens1(){
  __shared__ float sout[1536];
  __shared__ float ssc[288];
  int tid=threadIdx.x, lane=tid&31, wid=tid>>5;
  int l=blockIdx.x;
  for(int f=tid; f<1536; f+=256) sout[f]=g_r[l*1536+f];
  __syncthreads();
  // scores: warp owns th (3 per warp), pe hoisted, s-loop unrolled
  for(int th=wid; th<24; th+=8){
    const float* p=g_pe+th*128+lane;
    float p0=p[0], p1=p[32], p2=p[64], p3=p[96];
    float ck=g_cKe[th];
    #pragma unroll
    for(int s=0;s<12;s++){
      const float* o=sout+s*128+lane;
      float v=fmaf(p0,o[0],fmaf(p1,o[32],fmaf(p2,o[64],p3*o[96])));
      for(int off=16;off;off>>=1) v+=__shfl_xor_sync(0xffffffffu,v,off);
      if(lane==0) ssc[th*12+s]=v+ck;
    }
  }
  __syncthreads();
  if(tid<24){
    float* s=ssc+tid*12;
    float mx=-1e30f; for(int j=0;j<12;j++) mx=fmaxf(mx,s[j]);
    float sum=0.f; for(int j=0;j<12;j++){ float e=__expf(s[j]-mx); s[j]=e; sum+=e; }
    float inv=1.f/sum; for(int j=0;j<12;j++) s[j]*=inv;
  }
  __syncthreads();
  // obar: thread owns (d, th-half), s-outer: 12 LDS.32 + 144 broadcast-FMA
  int d=tid&127, thb=(tid>>7)*12;
  float acc[12];
  #pragma unroll
  for(int j=0;j<12;j++) acc[j]=0.f;
  #pragma unroll
  for(int s=0;s<12;s++){
    float v=sout[s*128+d];
    #pragma unroll
    for(int j=0;j<12;j++) acc[j]=fmaf(ssc[(thb+j)*12+s], v, acc[j]);
  }
  float* dst=g_xbar+l*3072+thb*128+d;
  #pragma unroll
  for(int j=0;j<12;j++) dst[j*128]=acc[j];
}

// ---------------- HMMA GEMM + LayerNorm: 96 rows (8 tokens)/CTA ----------------
#define SPITCH 136
__global__ void __launch_bounds__(384,1) k_hmma_ln(const float* __restrict__ gamma,
    const float* __restrict__ beta, float* __restrict__ out){
  extern __shared__ unsigned short smu16[];
  unsigned short* Ah = smu16;
  unsigned short* Al = Ah + 96*SPITCH;
  unsigned short* Bh = Al + 96*SPITCH;
  unsigned short* Bl = Bh + 128*SPITCH;
  float* Cs = (float*)smu16;
  __shared__ float sred[384];
  __shared__ float smean[8], srstd[8];
  int tid=threadIdx.x, w=tid>>5, lane=tid&31;
  int mw=w>>2, nw=w&3, g=lane>>2, t=lane&3;
  size_t rowBase=(size_t)blockIdx.x*96;
  float c[2][4][4];
  #pragma unroll
  for(int mi=0;mi<2;mi++)
    #pragma unroll
    for(int ni=0;ni<4;ni++){ c[mi][ni][0]=0.f;c[mi][ni][1]=0.f;c[mi][ni][2]=0.f;c[mi][ni][3]=0.f; }

  for(int chunk=0; chunk<2; chunk++){
    if(chunk) __syncthreads();
    for(int f=tid; f<3072; f+=384){
      int row=f>>5, kq=f&31;
      float4 v=*(const float4*)(g_xbar + (rowBase+row)*256 + chunk*128 + kq*4);
      uint32_t h01,h23,l01,l23;
      asm("cvt.rn.bf16x2.f32 %0,%1,%2;" : "=r"(h01) : "f"(v.y), "f"(v.x));
      asm("cvt.rn.bf16x2.f32 %0,%1,%2;" : "=r"(h23) : "f"(v.w), "f"(v.z));
      float hx=__uint_as_float(h01<<16), hy=__uint_as_float(h01&0xffff0000u);
      float hz=__uint_as_float(h23<<16), hw=__uint_as_float(h23&0xffff0000u);
      asm("cvt.rn.bf16x2.f32 %0,%1,%2;" : "=r"(l01) : "f"(v.y-hy), "f"(v.x-hx));
      asm("cvt.rn.bf16x2.f32 %0,%1,%2;" : "=r"(l23) : "f"(v.w-hw), "f"(v.z-hz));
      uint32_t off=row*SPITCH + kq*4;
      *(uint32_t*)(Ah+off)=h01; *(uint32_t*)(Ah+off+2)=h23;
      *(uint32_t*)(Al+off)=l01; *(uint32_t*)(Al+off+2)=l23;
    }
    for(int f=tid; f<8192; f+=384){
      int n=f>>6, kp=(f&63)*2;
      *(uint32_t*)(Bh+n*SPITCH+kp)=*(const uint32_t*)(g_Bh2+n*256+chunk*128+kp);
      *(uint32_t*)(Bl+n*SPITCH+kp)=*(const uint32_t*)(g_Bl2+n*256+chunk*128+kp);
    }
    __syncthreads();
    #pragma unroll
    for(int prod=0; prod<3; prod++){
      const unsigned short* As = (prod<2)? Ah : Al;
      const unsigned short* Bs = (prod==1)? Bl : Bh;
      #pragma unroll
      for(int ks=0; ks<8; ks++){
        int kb = ks*16;
        uint32_t a[2][4];
        #pragma unroll
        for(int mi=0;mi<2;mi++){
          int r0 = mw*32 + mi*16;
          a[mi][0]=*(const uint32_t*)(As+(r0+g  )*SPITCH + kb + 2*t);
          a[mi][1]=*(const uint32_t*)(As+(r0+g+8)*SPITCH + kb + 2*t);
          a[mi][2]=*(const uint32_t*)(As+(r0+g  )*SPITCH + kb + 8 + 2*t);
          a[mi][3]=*(const uint32_t*)(As+(r0+g+8)*SPITCH + kb + 8 + 2*t);
        }
        uint32_t b[4][2];
        #pragma unroll
        for(int ni=0;ni<4;ni++){
          int n0 = nw*32 + ni*8 + g;
          b[ni][0]=*(const uint32_t*)(Bs+n0*SPITCH + kb + 2*t);
          b[ni][1]=*(const uint32_t*)(Bs+n0*SPITCH + kb + 8 + 2*t);
        }
        #pragma unroll
        for(int mi=0;mi<2;mi++)
          #pragma unroll
          for(int ni=0;ni<4;ni++){
            asm volatile("mma.sync.aligned.m16n8k16.row.col.f32.bf16.bf16.f32 "
              "{%0,%1,%2,%3},{%4,%5,%6,%7},{%8,%9},{%0,%1,%2,%3};"
              : "+f"(c[mi][ni][0]),"+f"(c[mi][ni][1]),"+f"(c[mi][ni][2]),"+f"(c[mi][ni][3])
              : "r"(a[mi][0]),"r"(a[mi][1]),"r"(a[mi][2]),"r"(a[mi][3]),
                "r"(b[ni][0]),"r"(b[ni][1]));
          }
      }
    }
  }
  __syncthreads();
  #pragma unroll
  for(int mi=0;mi<2;mi++){
    #pragma unroll
    for(int ni=0;ni<4;ni++){
      int col = nw*32 + ni*8 + 2*t;
      float bi0=g_ce[col], bi1=g_ce[col+1];
      int r0 = mw*32 + mi*16 + g;
      Cs[r0*128+col]    =c[mi][ni][0]+bi0; Cs[r0*128+col+1]    =c[mi][ni][1]+bi1;
      Cs[(r0+8)*128+col]=c[mi][ni][2]+bi0; Cs[(r0+8)*128+col+1]=c[mi][ni][3]+bi1;
    }
  }
  __syncthreads();
  int tt=tid/48, sub=tid%48;
  float s1=0.f;
  #pragma unroll
  for(int j=0;j<32;j++) s1+=Cs[tt*1536+sub+48*j];
  sred[tid]=s1;
  __syncthreads();
  if(w<8){
    float v=sred[w*48+lane]+((lane<16)? sred[w*48+32+lane] : 0.f);
    for(int off=16;off;off>>=1) v+=__shfl_xor_sync(0xffffffffu,v,off);
    if(lane==0) smean[w]=v*(1.f/1536.f);
  }
  __syncthreads();
  float mu=smean[tt];
  float s2=0.f;
  #pragma unroll
  for(int j=0;j<32;j++){ float dd=Cs[tt*1536+sub+48*j]-mu; s2=fmaf(dd,dd,s2); }
  sred[tid]=s2;
  __syncthreads();
  if(w<8){
    float v=sred[w*48+lane]+((lane<16)? sred[w*48+32+lane] : 0.f);
    for(int off=16;off;off>>=1) v+=__shfl_xor_sync(0xffffffffu,v,off);
    if(lane==0) srstd[w]=rsqrtf(v*(1.f/1536.f)+1e-5f);
  }
  __syncthreads();
  for(int f=tid; f<12288; f+=384){
    int tk=f/1536, e=f%1536;
    out[rowBase*128 + f] = (Cs[f]-smean[tk])*srstd[tk]*gamma[e]+beta[e];
  }
}

extern "C" void kernel_launch(void* const* d_in, const int* in_sizes, int n_in,
                              void* d_out, int out_size){
  const float* x     =(const float*)d_in[0];
  const float* conv_w=(const float*)d_in[1];
  const float* conv_b=(const float*)d_in[2];
  const float* cemb  =(const float*)d_in[3];
  const float* cq    =(const float*)d_in[4];
  const float* gw    =(const float*)d_in[5];
  const float* gb    =(const float*)d_in[6];
  const float* gow   =(const float*)d_in[7];
  const float* gob   =(const float*)d_in[8];
  const float* eq    =(const float*)d_in[9];
  const float* ew    =(const float*)d_in[10];
  const float* eb    =(const float*)d_in[11];
  const float* eow   =(const float*)d_in[12];
  const float* eob   =(const float*)d_in[13];
  const float* gamma =(const float*)d_in[14];
  const float* beta  =(const float*)d_in[15];
  float* out=(float*)d_out;

  cudaFuncSetAttribute(k_main,    cudaFuncAttributeMaxDynamicSharedMemorySize, 66128);
  cudaFuncSetAttribute(k_hmma_ln, cudaFuncAttributeMaxDynamicSharedMemorySize, 121856);

  k_setupA<<<1717,256>>>(conv_b,cemb,cq,gw,gb,gow,gob,eq,ew,eb,eow,eob);
  k_cm<<<680,256>>>(conv_w,ew,eb,gw,gb);
  k_main<<<256,256,66128>>>(x);
  k_ens1<<<8192,256>>>();
  k_hmma_ln<<<1024,384,121856>>>(gamma,beta,out);
}

// round 17
// speedup vs baseline: 1.1257x; 1.0259x over previous
#include <cuda_runtime.h>
#include <cuda_bf16.h>
#include <cstdint>

#define NCC 68
#define SCALEF 0.125f

// ---------------- device scratch ----------------
__device__ float g_cbe[NCC*128];
__device__ float g_qg[12*128];
__device__ float g_qe[12*128];
__device__ float g_pe[24*128];
__device__ float g_cKe[24];
__device__ float g_MTg[12*2*128*128];
__device__ float g_cg[12*128];
__device__ float g_MTe[2*128*128];
__device__ float g_ce[128];
__device__ float g_coef2[206*5];
__device__ int   g_mm_cc[206];
__device__ float g_T[206*5*128];
__device__ float g_xbar[8192*12*256];
__device__ float g_r[8192*12*128];
__device__ unsigned short g_Bh2[128*256];
__device__ unsigned short g_Bl2[128*256];

__device__ __forceinline__ int grp_n(int i){ return i<5?7:(i<10?9:(i==10?17:6)); }
__device__ __forceinline__ int grp_s(int i){ return 2*(i<5? 7*i : (i<10? 35+9*(i-5) : (i==10? 80 : 97))); }
__device__ __forceinline__ int grp_off(int i){ int m=i%5; return m==0?3:(m==1?4:(m==2?2:(m==3?1:0))); }
__device__ __forceinline__ int member_cc(int i,int j){ return i<10 ? 5*j+grp_off(i) : (i==10?45+j:62+j); }
__device__ __forceinline__ int orig_ch(int cc){ return cc<45?cc:cc+20; }
__device__ __forceinline__ void m_decode(int m,int&ih,int&g,int&cc){
  for(int i=0;i<12;i++){ int n=grp_n(i); if(m<2*n){ int h=m/n; g=m%n; ih=2*i+h; cc=member_cc(i,g); return;} m-=2*n; }
  ih=0;g=0;cc=0;
}

// ---------------- setup A ----------------
__global__ void k_setupA(const float* __restrict__ cb,const float* __restrict__ cemb,
    const float* __restrict__ cq,const float* __restrict__ gw,const float* __restrict__ gb,
    const float* __restrict__ gow,const float* __restrict__ gob,const float* __restrict__ eq,
    const float* __restrict__ ew,const float* __restrict__ eb,const float* __restrict__ eow,
    const float* __restrict__ eob){
  int idx = blockIdx.x*256+threadIdx.x;
  if(idx<8704){ int cc=idx>>7,d=idx&127,c=orig_ch(cc); g_cbe[idx]=cb[c*128+d]+cemb[c*128+d]; return;}
  idx-=8704;
  if(idx<1536){ int i=idx>>7,r=idx&127; float s=gb[i*384+r];
    const float* w=gw+(i*384+r)*128; const float* q=cq+i*128;
    for(int d=0;d<128;d++) s=fmaf(q[d],w[d],s); g_qg[i*128+r]=s; return;}
  idx-=1536;
  if(idx<1536){ int t=idx>>7,r=idx&127; float s=eb[r];
    const float* w=ew+r*128; const float* q=eq+t*128;
    for(int d=0;d<128;d++) s=fmaf(q[d],w[d],s); g_qe[t*128+r]=s; return;}
  idx-=1536;
  if(idx<393216){ int i=idx>>15, rem=idx&32767, h=rem>>14, dout=(rem>>7)&127, k=rem&127;
    float s=0.f; const float* gr=gow+i*16384+dout*128+h*64;
    for(int e=0;e<64;e++) s=fmaf(gr[e], gw[(i*384+256+h*64+e)*128+k], s);
    g_MTg[((i*2+h)*128+k)*128+dout]=s; return;}
  idx-=393216;
  if(idx<1536){ int i=idx>>7,dout=idx&127; float s=gob[i*128+dout];
    const float* gr=gow+i*16384+dout*128;
    for(int r=0;r<128;r++) s=fmaf(gr[r], gb[i*384+256+r], s); g_cg[idx]=s; return;}
  idx-=1536;
  if(idx<32768){ int h=idx>>14, dout=(idx>>7)&127, k=idx&127;
    float s=0.f; const float* er=eow+dout*128+h*64;
    for(int e=0;e<64;e++) s=fmaf(er[e], ew[(256+h*64+e)*128+k], s);
    g_MTe[(h*128+k)*128+dout]=s; return;}
  idx-=32768;
  if(idx<128){ float s=eob[idx]; const float* er=eow+idx*128;
    for(int r=0;r<128;r++) s=fmaf(er[r], eb[256+r], s); g_ce[idx]=s;}
}

// ---------------- merged setup: misc (blocks 0..655) + coef (blocks 656..679) ----------------
__global__ void k_cm(const float* __restrict__ conv_w,const float* __restrict__ ew,
                     const float* __restrict__ eb,const float* __restrict__ gw,
                     const float* __restrict__ gb){
  if(blockIdx.x<656){
    int idx=blockIdx.x*256+threadIdx.x;
    if(idx<131840){
      int m=idx/640, p=(idx/128)%5, dout=idx&127;
      int ih,g,cc; m_decode(m,ih,g,cc);
      const float* M=g_MTg+ih*16384;
      float s=0.f;
      if(p<4){ const float* w=conv_w+(orig_ch(cc)*4+p)*128;
        for(int k=0;k<128;k++) s=fmaf(w[k], M[k*128+dout], s);
      } else { const float* w=g_cbe+cc*128;
        for(int k=0;k<128;k++) s=fmaf(w[k], M[k*128+dout], s);
      }
      g_T[idx]=s; return;
    }
    idx-=131840;
    if(idx<32768){
      int n=idx>>8, k=idx&255;
      float v=g_MTe[k*128+n];
      uint32_t hp; asm("cvt.rn.bf16x2.f32 %0,%1,%2;" : "=r"(hp) : "f"(0.f), "f"(v));
      float vh=__uint_as_float(hp<<16);
      float lo=v-vh;
      uint32_t lp; asm("cvt.rn.bf16x2.f32 %0,%1,%2;" : "=r"(lp) : "f"(0.f), "f"(lo));
      g_Bh2[n*256+k]=(unsigned short)(hp&0xffffu);
      g_Bl2[n*256+k]=(unsigned short)(lp&0xffffu);
      return;
    }
    idx-=32768;
    if(idx<3072){
      int th=idx>>7,d=idx&127,t=th>>1,h=th&1;
      float s=0.f; const float* q=g_qe+t*128+h*64;
      for(int e=0;e<64;e++) s=fmaf(q[e], ew[(128+h*64+e)*128+d], s);
      g_pe[idx]=s*SCALEF; return;
    }
    idx-=3072;
    if(idx<24){
      int t=idx>>1,h=idx&1; float s=0.f; const float* q=g_qe+t*128+h*64;
      for(int e=0;e<64;e++) s=fmaf(q[e], eb[128+h*64+e], s);
      g_cKe[idx]=s*SCALEF;
    }
    return;
  }
  __shared__ float sred[4];
  int ih=blockIdx.x-656, i=ih>>1, h=ih&1, d=threadIdx.x;
  bool act = d<128;
  const float* q=g_qg+i*128+h*64;
  float pv=0.f, ck=0.f;
  if(act){
    for(int e=0;e<64;e++) pv=fmaf(q[e], gw[(i*384+128+h*64+e)*128+d], pv);
    pv*=SCALEF;
    for(int e=0;e<64;e++) ck=fmaf(q[e], gb[i*384+128+h*64+e], ck);
    ck*=SCALEF;
  }
  int n=grp_n(i), ms=grp_s(i)+h*n;
  for(int g=0;g<n;g++){
    int cc=member_cc(i,g);
    for(int p=0;p<5;p++){
      if(act){
        float w = (p<4)? conv_w[(orig_ch(cc)*4+p)*128+d] : g_cbe[cc*128+d];
        float v = pv*w;
        for(int off=16;off;off>>=1) v+=__shfl_xor_sync(0xffffffffu,v,off);
        if((d&31)==0) sred[d>>5]=v;
      }
      __syncthreads();
      if(d==0){
        float s=sred[0]+sred[1]+sred[2]+sred[3];
        if(p==4) s+=ck;
        g_coef2[(ms+g)*5+p]=s;
        g_mm_cc[ms+g]=cc;
      }
      __syncthreads();
    }
  }
}

// ---------------- K-main: r12 form ----------------
__global__ void __launch_bounds__(256,3) k_main(const float* __restrict__ x){
  extern __shared__ float sm[];
  float* sp  = sm;             // 8704
  float* sa  = sm + 8704;      // 6592
  float* scf = sm + 15296;     // 1030
  int*   scc = (int*)(sm + 16326); // 206
  int tid=threadIdx.x;
  int hp = blockIdx.x>>2, wb = blockIdx.x&3;
  for(int f=tid; f<8704; f+=256){
    int cc=f>>7, r=f&127, pi=r>>6, j=r&63, t=j>>1, pj=j&1;
    sp[(cc*4+pi*2+pj)*32+t] = x[orig_ch(cc)*32768 + (2*hp+pi)*256 + wb*64 + j];
  }
  for(int f=tid; f<1030; f+=256) scf[f]=g_coef2[f];
  if(tid<206) scc[tid]=g_mm_cc[tid];
  __syncthreads();
  for(int f=tid; f<6592; f+=256){
    int m=f>>5, t=f&31;
    const float* cf=scf+m*5;
    const float* pb=sp+scc[m]*128;
    sa[f]=fmaf(cf[0],pb[t],fmaf(cf[1],pb[32+t],fmaf(cf[2],pb[64+t],fmaf(cf[3],pb[96+t],cf[4]))));
  }
  __syncthreads();
  for(int f=tid; f<768; f+=256){
    int j=f>>5, t=f&31, i=j>>1, h=j&1;
    int n=grp_n(i), st=grp_s(i)+h*n;
    float mx=-1e30f;
    for(int g=0;g<n;g++) mx=fmaxf(mx, sa[(st+g)*32+t]);
    float sum=0.f;
    for(int g=0;g<n;g++){ float e=__expf(sa[(st+g)*32+t]-mx); sa[(st+g)*32+t]=e; sum+=e; }
    float inv=1.f/sum;
    for(int g=0;g<n;g++) sa[(st+g)*32+t]*=inv;
  }
  __syncthreads();
  int d=tid&127, th=tid>>7;
  int l0=blockIdx.x*32 + th*16;
  for(int i=0;i<12;i++){
    float acc[16];
    float bias=g_cg[i*128+d];
    #pragma unroll
    for(int t=0;t<16;t++) acc[t]=bias;
    int st=grp_s(i), n=grp_n(i);
    for(int g=0;g<n;g++){
      int m0=st+g, m1=m0+n;
      const float* Ta=g_T+m0*640+d;
      const float* Tb=g_T+m1*640+d;
      float A0=Ta[0],A1=Ta[128],A2=Ta[256],A3=Ta[384],A4=Ta[512];
      float B0=Tb[0],B1=Tb[128],B2=Tb[256],B3=Tb[384],B4=Tb[512];
      const float* pb=sp+scc[m0]*128+th*16;
      const float* aa=sa+m0*32+th*16;
      const float* ab=sa+m1*32+th*16;
      #pragma unroll
      for(int q=0;q<4;q++){
        float4 p0=*(const float4*)(pb+q*4);
        float4 p1=*(const float4*)(pb+32+q*4);
        float4 p2=*(const float4*)(pb+64+q*4);
        float4 p3=*(const float4*)(pb+96+q*4);
        float4 av0=*(const float4*)(aa+q*4);
        float4 av1=*(const float4*)(ab+q*4);
        float ia,ib;
        ia=fmaf(A0,p0.x,fmaf(A1,p1.x,fmaf(A2,p2.x,fmaf(A3,p3.x,A4))));
        ib=fmaf(B0,p0.x,fmaf(B1,p1.x,fmaf(B2,p2.x,fmaf(B3,p3.x,B4))));
        acc[q*4+0]=fmaf(av0.x,ia,fmaf(av1.x,ib,acc[q*4+0]));
        ia=fmaf(A0,p0.y,fmaf(A1,p1.y,fmaf(A2,p2.y,fmaf(A3,p3.y,A4))));
        ib=fmaf(B0,p0.y,fmaf(B1,p1.y,fmaf(B2,p2.y,fmaf(B3,p3.y,B4))));
        acc[q*4+1]=fmaf(av0.y,ia,fmaf(av1.y,ib,acc[q*4+1]));
        ia=fmaf(A0,p0.z,fmaf(A1,p1.z,fmaf(A2,p2.z,fmaf(A3,p3.z,A4))));
        ib=fmaf(B0,p0.z,fmaf(B1,p1.z,fmaf(B2,p2.z,fmaf(B3,p3.z,B4))));
        acc[q*4+2]=fmaf(av0.z,ia,fmaf(av1.z,ib,acc[q*4+2]));
        ia=fmaf(A0,p0.w,fmaf(A1,p1.w,fmaf(A2,p2.w,fmaf(A3,p3.w,A4))));
        ib=fmaf(B0,p0.w,fmaf(B1,p1.w,fmaf(B2,p2.w,fmaf(B3,p3.w,B4))));
        acc[q*4+3]=fmaf(av0.w,ia,fmaf(av1.w,ib,acc[q*4+3]));
      }
    }
    #pragma unroll
    for(int t=0;t<16;t++)
      g_r[((l0+t)*12+i)*128+d]=acc[t];
  }
}

// ---------------- ensemble scores + obar (sscT transposed, float4 weight loads) ----------------
__global__ void __launch_bounds__(256,5) k_ens1(){
  __shared__ float sout[1536];
  __shared__ float ssc[288];       // [th][s] raw scores
  __shared__ float sscT[288];      // [s][th] softmaxed, for float4 obar loads
  int tid=threadIdx.x, lane=tid&31, wid=tid>>5;
  int l=blockIdx.x;
  for(int f=tid; f<1536; f+=256) sout[f]=g_r[l*1536+f];
  __syncthreads();
  for(int th=wid; th<24; th+=8){
    const float* p=g_pe+th*128+lane;
    float p0=p[0], p1=p[32], p2=p[64], p3=p[96];
    float ck=g_cKe[th];
    #pragma unroll
    for(int s=0;s<12;s++){
      const float* o=sout+s*128+lane;
      float v=fmaf(p0,o[0],fmaf(p1,o[32],fmaf(p2,o[64],p3*o[96])));
      for(int off=16;off;off>>=1) v+=__shfl_xor_sync(0xffffffffu,v,off);
      if(lane==0) ssc[th*12+s]=v+ck;
    }
  }
  __syncthreads();
  if(tid<24){
    float* s=ssc+tid*12;
    float mx=-1e30f; for(int j=0;j<12;j++) mx=fmaxf(mx,s[j]);
    float sum=0.f; for(int j=0;j<12;j++){ float e=__expf(s[j]-mx); s[j]=e; sum+=e; }
    float inv=1.f/sum;
    for(int j=0;j<12;j++) sscT[j*24+tid]=s[j]*inv;
  }
  __syncthreads();
  int d=tid&127, thb=(tid>>7)*12;
  float acc[12];
  #pragma unroll
  for(int j=0;j<12;j++) acc[j]=0.f;
  #pragma unroll
  for(int s=0;s<12;s++){
    float v=sout[s*128+d];
    const float* wr=sscT+s*24+thb;
    float4 w0=*(const float4*)wr;
    float4 w1=*(const float4*)(wr+4);
    float4 w2=*(const float4*)(wr+8);
    acc[0]=fmaf(w0.x,v,acc[0]); acc[1]=fmaf(w0.y,v,acc[1]);
    acc[2]=fmaf(w0.z,v,acc[2]); acc[3]=fmaf(w0.w,v,acc[3]);
    acc[4]=fmaf(w1.x,v,acc[4]); acc[5]=fmaf(w1.y,v,acc[5]);
    acc[6]=fmaf(w1.z,v,acc[6]); acc[7]=fmaf(w1.w,v,acc[7]);
    acc[8]=fmaf(w2.x,v,acc[8]); acc[9]=fmaf(w2.y,v,acc[9]);
    acc[10]=fmaf(w2.z,v,acc[10]); acc[11]=fmaf(w2.w,v,acc[11]);
  }
  float* dst=g_xbar+l*3072+thb*128+d;
  #pragma unroll
  for(int j=0;j<12;j++) dst[j*128]=acc[j];
}

// ---------------- HMMA GEMM + LayerNorm: 96 rows (8 tokens)/CTA ----------------
#define SPITCH 136
__global__ void __launch_bounds__(384,1) k_hmma_ln(const float* __restrict__ gamma,
    const float* __restrict__ beta, float* __restrict__ out){
  extern __shared__ unsigned short smu16[];
  unsigned short* Ah = smu16;
  unsigned short* Al = Ah + 96*SPITCH;
  unsigned short* Bh = Al + 96*SPITCH;
  unsigned short* Bl = Bh + 128*SPITCH;
  float* Cs = (float*)smu16;
  __shared__ float sred[384];
  __shared__ float smean[8], srstd[8];
  int tid=threadIdx.x, w=tid>>5, lane=tid&31;
  int mw=w>>2, nw=w&3, g=lane>>2, t=lane&3;
  size_t rowBase=(size_t)blockIdx.x*96;
  float c[2][4][4];
  #pragma unroll
  for(int mi=0;mi<2;mi++)
    #pragma unroll
    for(int ni=0;ni<4;ni++){ c[mi][ni][0]=0.f;c[mi][ni][1]=0.f;c[mi][ni][2]=0.f;c[mi][ni][3]=0.f; }

  for(int chunk=0; chunk<2; chunk++){
    if(chunk) __syncthreads();
    for(int f=tid; f<3072; f+=384){
      int row=f>>5, kq=f&31;
      float4 v=*(const float4*)(g_xbar + (rowBase+row)*256 + chunk*128 + kq*4);
      uint32_t h01,h23,l01,l23;
      asm("cvt.rn.bf16x2.f32 %0,%1,%2;" : "=r"(h01) : "f"(v.y), "f"(v.x));
      asm("cvt.rn.bf16x2.f32 %0,%1,%2;" : "=r"(h23) : "f"(v.w), "f"(v.z));
      float hx=__uint_as_float(h01<<16), hy=__uint_as_float(h01&0xffff0000u);
      float hz=__uint_as_float(h23<<16), hw=__uint_as_float(h23&0xffff0000u);
      asm("cvt.rn.bf16x2.f32 %0,%1,%2;" : "=r"(l01) : "f"(v.y-hy), "f"(v.x-hx));
      asm("cvt.rn.bf16x2.f32 %0,%1,%2;" : "=r"(l23) : "f"(v.w-hw), "f"(v.z-hz));
      uint32_t off=row*SPITCH + kq*4;
      *(uint32_t*)(Ah+off)=h01; *(uint32_t*)(Ah+off+2)=h23;
      *(uint32_t*)(Al+off)=l01; *(uint32_t*)(Al+off+2)=l23;
    }
    for(int f=tid; f<8192; f+=384){
      int n=f>>6, kp=(f&63)*2;
      *(uint32_t*)(Bh+n*SPITCH+kp)=*(const uint32_t*)(g_Bh2+n*256+chunk*128+kp);
      *(uint32_t*)(Bl+n*SPITCH+kp)=*(const uint32_t*)(g_Bl2+n*256+chunk*128+kp);
    }
    __syncthreads();
    #pragma unroll
    for(int prod=0; prod<3; prod++){
      const unsigned short* As = (prod<2)? Ah : Al;
      const unsigned short* Bs = (prod==1)? Bl : Bh;
      #pragma unroll
      for(int ks=0; ks<8; ks++){
        int kb = ks*16;
        uint32_t a[2][4];
        #pragma unroll
        for(int mi=0;mi<2;mi++){
          int r0 = mw*32 + mi*16;
          a[mi][0]=*(const uint32_t*)(As+(r0+g  )*SPITCH + kb + 2*t);
          a[mi][1]=*(const uint32_t*)(As+(r0+g+8)*SPITCH + kb + 2*t);
          a[mi][2]=*(const uint32_t*)(As+(r0+g  )*SPITCH + kb + 8 + 2*t);
          a[mi][3]=*(const uint32_t*)(As+(r0+g+8)*SPITCH + kb + 8 + 2*t);
        }
        uint32_t b[4][2];
        #pragma unroll
        for(int ni=0;ni<4;ni++){
          int n0 = nw*32 + ni*8 + g;
          b[ni][0]=*(const uint32_t*)(Bs+n0*SPITCH + kb + 2*t);
          b[ni][1]=*(const uint32_t*)(Bs+n0*SPITCH + kb + 8 + 2*t);
        }
        #pragma unroll
        for(int mi=0;mi<2;mi++)
          #pragma unroll
          for(int ni=0;ni<4;ni++){
            asm volatile("mma.sync.aligned.m16n8k16.row.col.f32.bf16.bf16.f32 "
              "{%0,%1,%2,%3},{%4,%5,%6,%7},{%8,%9},{%0,%1,%2,%3};"
              : "+f"(c[mi][ni][0]),"+f"(c[mi][ni][1]),"+f"(c[mi][ni][2]),"+f"(c[mi][ni][3])
              : "r"(a[mi][0]),"r"(a[mi][1]),"r"(a[mi][2]),"r"(a[mi][3]),
                "r"(b[ni][0]),"r"(b[ni][1]));
          }
      }
    }
  }
  __syncthreads();
  #pragma unroll
  for(int mi=0;mi<2;mi++){
    #pragma unroll
    for(int ni=0;ni<4;ni++){
      int col = nw*32 + ni*8 + 2*t;
      float bi0=g_ce[col], bi1=g_ce[col+1];
      int r0 = mw*32 + mi*16 + g;
      Cs[r0*128+col]    =c[mi][ni][0]+bi0; Cs[r0*128+col+1]    =c[mi][ni][1]+bi1;
      Cs[(r0+8)*128+col]=c[mi][ni][2]+bi0; Cs[(r0+8)*128+col+1]=c[mi][ni][3]+bi1;
    }
  }
  __syncthreads();
  int tt=tid/48, sub=tid%48;
  float s1=0.f;
  #pragma unroll
  for(int j=0;j<32;j++) s1+=Cs[tt*1536+sub+48*j];
  sred[tid]=s1;
  __syncthreads();
  if(w<8){
    float v=sred[w*48+lane]+((lane<16)? sred[w*48+32+lane] : 0.f);
    for(int off=16;off;off>>=1) v+=__shfl_xor_sync(0xffffffffu,v,off);
    if(lane==0) smean[w]=v*(1.f/1536.f);
  }
  __syncthreads();
  float mu=smean[tt];
  float s2=0.f;
  #pragma unroll
  for(int j=0;j<32;j++){ float dd=Cs[tt*1536+sub+48*j]-mu; s2=fmaf(dd,dd,s2); }
  sred[tid]=s2;
  __syncthreads();
  if(w<8){
    float v=sred[w*48+lane]+((lane<16)? sred[w*48+32+lane] : 0.f);
    for(int off=16;off;off>>=1) v+=__shfl_xor_sync(0xffffffffu,v,off);
    if(lane==0) srstd[w]=rsqrtf(v*(1.f/1536.f)+1e-5f);
  }
  __syncthreads();
  for(int f=tid; f<12288; f+=384){
    int tk=f/1536, e=f%1536;
    out[rowBase*128 + f] = (Cs[f]-smean[tk])*srstd[tk]*gamma[e]+beta[e];
  }
}

extern "C" void kernel_launch(void* const* d_in, const int* in_sizes, int n_in,
                              void* d_out, int out_size){
  const float* x     =(const float*)d_in[0];
  const float* conv_w=(const float*)d_in[1];
  const float* conv_b=(const float*)d_in[2];
  const float* cemb  =(const float*)d_in[3];
  const float* cq    =(const float*)d_in[4];
  const float* gw    =(const float*)d_in[5];
  const float* gb    =(const float*)d_in[6];
  const float* gow   =(const float*)d_in[7];
  const float* gob   =(const float*)d_in[8];
  const float* eq    =(const float*)d_in[9];
  const float* ew    =(const float*)d_in[10];
  const float* eb    =(const float*)d_in[11];
  const float* eow   =(const float*)d_in[12];
  const float* eob   =(const float*)d_in[13];
  const float* gamma =(const float*)d_in[14];
  const float* beta  =(const float*)d_in[15];
  float* out=(float*)d_out;

  cudaFuncSetAttribute(k_main,    cudaFuncAttributeMaxDynamicSharedMemorySize, 66128);
  cudaFuncSetAttribute(k_hmma_ln, cudaFuncAttributeMaxDynamicSharedMemorySize, 121856);

  k_setupA<<<1717,256>>>(conv_b,cemb,cq,gw,gb,gow,gob,eq,ew,eb,eow,eob);
  k_cm<<<680,256>>>(conv_w,ew,eb,gw,gb);
  k_main<<<256,256,66128>>>(x);
  k_ens1<<<8192,256>>>();
  k_hmma_ln<<<1024,384,121856>>>(gamma,beta,out);
}